// round 1
// baseline (speedup 1.0000x reference)
#include <cuda_runtime.h>

// Problem constants
#define TT    128   // time steps
#define BB    256   // batch
#define DG    512   // input dim
#define DH    1024  // hidden dim
#define LN_EPS 1e-5f

// GEMM tiling
#define BM 128
#define BN 128
#define BK 16
#define NSPLIT 8
#define KSLICE (DH / NSPLIT)   // 128

// Scratch: per-split partial products of the recurrent GEMM (deterministic, no atomics)
__device__ float g_partials[NSPLIT * BB * DH];   // 8 MB

// ---------------------------------------------------------------------------
// Tiled fp32 GEMM: C[M,N] = A[M,K_A] * Bw[N,K_B]^T  (row-major A and Bw, both
// K-contiguous). 128x128 tile, BK=16, 256 threads, 8x8 register blocking,
// register software-pipeline on global loads.
//
// TO_PARTIAL: write to g_partials[blockIdx.z] slice, kbase = z*ksize (split-K).
// ADD_BIAS:   add bias[n] on store (used by the zg projection).
// ---------------------------------------------------------------------------
template<bool ADD_BIAS, bool TO_PARTIAL>
__global__ __launch_bounds__(256) void gemm_kernel(
    const float* __restrict__ A, int lda,
    const float* __restrict__ Bw, int ldb,
    const float* __restrict__ bias,
    float* __restrict__ Cbase, int ldc,
    int ksize)
{
    __shared__ float As[BK][BM + 4];
    __shared__ float Bs[BK][BN + 4];

    const int tid = threadIdx.x;
    const int tx  = tid & 15;        // 0..15 -> n groups
    const int ty  = tid >> 4;        // 0..15 -> m groups

    const int m0 = blockIdx.y * BM;
    const int n0 = blockIdx.x * BN;
    const int kb = TO_PARTIAL ? (blockIdx.z * ksize) : 0;

    const float* Ap = A  + (size_t)m0 * lda + kb;
    const float* Bp = Bw + (size_t)n0 * ldb + kb;

    float* C;
    if (TO_PARTIAL) {
        C = &g_partials[(size_t)blockIdx.z * (BB * DH)];
    } else {
        C = Cbase;
    }

    // loader indices: 512 float4 per operand tile, 2 per thread
    const int r0 = tid >> 2;          // 0..63
    const int c4 = tid & 3;           // 0..3 (float4 column group)

    float acc[8][8];
    #pragma unroll
    for (int i = 0; i < 8; i++)
        #pragma unroll
        for (int j = 0; j < 8; j++) acc[i][j] = 0.f;

    // prologue: load tile 0 into registers
    float4 av0 = *(const float4*)(Ap + (size_t)r0        * lda + c4 * 4);
    float4 av1 = *(const float4*)(Ap + (size_t)(r0 + 64) * lda + c4 * 4);
    float4 bv0 = *(const float4*)(Bp + (size_t)r0        * ldb + c4 * 4);
    float4 bv1 = *(const float4*)(Bp + (size_t)(r0 + 64) * ldb + c4 * 4);

    for (int kt = 0; kt < ksize; kt += BK) {
        __syncthreads();   // previous tile fully consumed
        // store registers -> smem (transposed: [k][m] / [k][n])
        As[c4 * 4 + 0][r0]      = av0.x;
        As[c4 * 4 + 1][r0]      = av0.y;
        As[c4 * 4 + 2][r0]      = av0.z;
        As[c4 * 4 + 3][r0]      = av0.w;
        As[c4 * 4 + 0][r0 + 64] = av1.x;
        As[c4 * 4 + 1][r0 + 64] = av1.y;
        As[c4 * 4 + 2][r0 + 64] = av1.z;
        As[c4 * 4 + 3][r0 + 64] = av1.w;
        Bs[c4 * 4 + 0][r0]      = bv0.x;
        Bs[c4 * 4 + 1][r0]      = bv0.y;
        Bs[c4 * 4 + 2][r0]      = bv0.z;
        Bs[c4 * 4 + 3][r0]      = bv0.w;
        Bs[c4 * 4 + 0][r0 + 64] = bv1.x;
        Bs[c4 * 4 + 1][r0 + 64] = bv1.y;
        Bs[c4 * 4 + 2][r0 + 64] = bv1.z;
        Bs[c4 * 4 + 3][r0 + 64] = bv1.w;
        __syncthreads();

        // prefetch next tile (LDG latency overlaps the FMA loop below)
        if (kt + BK < ksize) {
            const float* Apn = Ap + kt + BK;
            const float* Bpn = Bp + kt + BK;
            av0 = *(const float4*)(Apn + (size_t)r0        * lda + c4 * 4);
            av1 = *(const float4*)(Apn + (size_t)(r0 + 64) * lda + c4 * 4);
            bv0 = *(const float4*)(Bpn + (size_t)r0        * ldb + c4 * 4);
            bv1 = *(const float4*)(Bpn + (size_t)(r0 + 64) * ldb + c4 * 4);
        }

        #pragma unroll
        for (int kk = 0; kk < BK; kk++) {
            float a[8], b[8];
            *(float4*)(a)     = *(const float4*)&As[kk][ty * 8];
            *(float4*)(a + 4) = *(const float4*)&As[kk][ty * 8 + 4];
            *(float4*)(b)     = *(const float4*)&Bs[kk][tx * 8];
            *(float4*)(b + 4) = *(const float4*)&Bs[kk][tx * 8 + 4];
            #pragma unroll
            for (int i = 0; i < 8; i++)
                #pragma unroll
                for (int j = 0; j < 8; j++)
                    acc[i][j] = fmaf(a[i], b[j], acc[i][j]);
        }
    }

    // epilogue
    #pragma unroll
    for (int i = 0; i < 8; i++) {
        const int row = m0 + ty * 8 + i;
        float* Crow = C + (size_t)row * ldc + n0 + tx * 8;
        #pragma unroll
        for (int j = 0; j < 8; j += 4) {
            float4 v;
            v.x = acc[i][j + 0];
            v.y = acc[i][j + 1];
            v.z = acc[i][j + 2];
            v.w = acc[i][j + 3];
            if (ADD_BIAS) {
                const int col = n0 + tx * 8 + j;
                v.x += bias[col + 0];
                v.y += bias[col + 1];
                v.z += bias[col + 2];
                v.w += bias[col + 3];
            }
            *(float4*)(Crow + j) = v;
        }
    }
}

// ---------------------------------------------------------------------------
// LayerNorm + ReLU over rows of length DH.
// io holds zg_t on entry; pre = zg_t + sum_s partials[s]; out = relu(LN(pre)).
// One CTA per row, 256 threads, 4 columns/thread. nsplit==0 for t==0 (h0=0).
// ---------------------------------------------------------------------------
__global__ __launch_bounds__(256) void ln_kernel(
    float* __restrict__ io,
    int nsplit,
    const float* __restrict__ gamma,
    const float* __restrict__ beta)
{
    const int row  = blockIdx.x;
    const int tid  = threadIdx.x;
    const int base = row * DH;

    float v[4];
    #pragma unroll
    for (int j = 0; j < 4; j++) {
        const int c = tid + j * 256;
        float x = io[base + c];
        for (int s = 0; s < nsplit; s++)
            x += g_partials[(size_t)s * (BB * DH) + base + c];
        v[j] = x;
    }

    float s1 = 0.f, s2 = 0.f;
    #pragma unroll
    for (int j = 0; j < 4; j++) { s1 += v[j]; s2 += v[j] * v[j]; }

    // warp reduce
    #pragma unroll
    for (int o = 16; o > 0; o >>= 1) {
        s1 += __shfl_xor_sync(0xffffffffu, s1, o);
        s2 += __shfl_xor_sync(0xffffffffu, s2, o);
    }
    __shared__ float red1[8], red2[8];
    const int wid  = tid >> 5;
    const int lane = tid & 31;
    if (lane == 0) { red1[wid] = s1; red2[wid] = s2; }
    __syncthreads();
    if (wid == 0) {
        float a = (lane < 8) ? red1[lane] : 0.f;
        float b = (lane < 8) ? red2[lane] : 0.f;
        #pragma unroll
        for (int o = 4; o > 0; o >>= 1) {
            a += __shfl_xor_sync(0xffffffffu, a, o);
            b += __shfl_xor_sync(0xffffffffu, b, o);
        }
        if (lane == 0) { red1[0] = a; red2[0] = b; }
    }
    __syncthreads();

    const float mean = red1[0] * (1.0f / DH);
    const float var  = red2[0] * (1.0f / DH) - mean * mean;
    const float inv  = rsqrtf(var + LN_EPS);

    #pragma unroll
    for (int j = 0; j < 4; j++) {
        const int c = tid + j * 256;
        float y = (v[j] - mean) * inv * gamma[c] + beta[c];
        io[base + c] = fmaxf(y, 0.f);
    }
}

// ---------------------------------------------------------------------------
// kernel_launch: zg projection -> in-place per-step (split-K GEMM + LN/ReLU)
// ---------------------------------------------------------------------------
extern "C" void kernel_launch(void* const* d_in, const int* in_sizes, int n_in,
                              void* d_out, int out_size)
{
    const float* z     = (const float*)d_in[0];   // [T,B,DG]
    const float* W_h   = (const float*)d_in[1];   // [DH,DH]
    const float* W_g   = (const float*)d_in[2];   // [DH,DG]
    const float* b_h   = (const float*)d_in[3];   // [DH]
    const float* gamma = (const float*)d_in[4];   // [DH]
    const float* beta  = (const float*)d_in[5];   // [DH]
    float* out = (float*)d_out;                   // [T,B,DH]

    // 1) zg = z @ W_g^T + b_h  -> written straight into d_out
    {
        dim3 grid(DH / BN, (TT * BB) / BM, 1);
        gemm_kernel<true, false><<<grid, 256>>>(z, DG, W_g, DG, b_h,
                                                out, DH, DG);
    }

    // 2) t = 0: h0 = 0, so pre = zg_0 -> LN+ReLU in place
    ln_kernel<<<BB, 256>>>(out, 0, gamma, beta);

    // 3) recurrence
    for (int t = 1; t < TT; t++) {
        float* h_prev = out + (size_t)(t - 1) * BB * DH;
        float* zg_t   = out + (size_t)t * BB * DH;
        dim3 grid(DH / BN, BB / BM, NSPLIT);
        gemm_kernel<false, true><<<grid, 256>>>(h_prev, DH, W_h, DH, nullptr,
                                                nullptr, DH, KSLICE);
        ln_kernel<<<BB, 256>>>(zg_t, NSPLIT, gamma, beta);
    }
}

// round 6
// speedup vs baseline: 1.8829x; 1.8829x over previous
#include <cuda_runtime.h>
#include <cuda_bf16.h>
#include <mma.h>
#include <cstdint>

using namespace nvcuda;

#define TT 128
#define BB 256
#define DG 512
#define DH 1024
#define LN_EPS 1e-5f

#define BM 64
#define BN 128
#define BK 32
#define APITCH 40                 // smem row pitch in bf16 elements (80 B)
#define NSPLIT 4
#define KS (DH / NSPLIT)          // 256

// ---------------------------------------------------------------------------
// Device scratch (referenced ONLY from device code — never passed from host)
// ---------------------------------------------------------------------------
__device__ __align__(256) __nv_bfloat16 g_zhi[TT * BB * DG];
__device__ __align__(256) __nv_bfloat16 g_zlo[TT * BB * DG];
__device__ __align__(256) __nv_bfloat16 g_whh_hi[DH * DH];
__device__ __align__(256) __nv_bfloat16 g_whh_lo[DH * DH];
__device__ __align__(256) __nv_bfloat16 g_wg_hi[DH * DG];
__device__ __align__(256) __nv_bfloat16 g_wg_lo[DH * DG];
__device__ __align__(256) __nv_bfloat16 g_hhi[BB * DH];
__device__ __align__(256) __nv_bfloat16 g_hlo[BB * DH];
__device__ __align__(256) float g_partials[NSPLIT * BB * DH];

// ---------------------------------------------------------------------------
// cp.async helpers (family-portable)
// ---------------------------------------------------------------------------
__device__ __forceinline__ void cp16(uint32_t s, const void* g) {
    asm volatile("cp.async.cg.shared.global [%0], [%1], 16;" :: "r"(s), "l"(g));
}
__device__ __forceinline__ void cp_commit() {
    asm volatile("cp.async.commit_group;" ::: "memory");
}
template<int N>
__device__ __forceinline__ void cp_wait() {
    asm volatile("cp.async.wait_group %0;" :: "n"(N) : "memory");
}

// ---------------------------------------------------------------------------
// fp32 -> bf16 hi/lo split kernels. TARGET: 0=z, 1=W_h, 2=W_g
// ---------------------------------------------------------------------------
template<int TARGET>
__global__ __launch_bounds__(256) void split_kernel(const float* __restrict__ src, int n4) {
    int i = blockIdx.x * 256 + threadIdx.x;
    if (i >= n4) return;
    __nv_bfloat16* hi;
    __nv_bfloat16* lo;
    if (TARGET == 0) { hi = g_zhi;    lo = g_zlo; }
    if (TARGET == 1) { hi = g_whh_hi; lo = g_whh_lo; }
    if (TARGET == 2) { hi = g_wg_hi;  lo = g_wg_lo; }
    float4 v = ((const float4*)src)[i];
    __nv_bfloat16 h0 = __float2bfloat16(v.x);
    __nv_bfloat16 h1 = __float2bfloat16(v.y);
    __nv_bfloat16 h2 = __float2bfloat16(v.z);
    __nv_bfloat16 h3 = __float2bfloat16(v.w);
    __nv_bfloat162 p;
    p.x = h0; p.y = h1; ((__nv_bfloat162*)hi)[i * 2]     = p;
    p.x = h2; p.y = h3; ((__nv_bfloat162*)hi)[i * 2 + 1] = p;
    p.x = __float2bfloat16(v.x - __bfloat162float(h0));
    p.y = __float2bfloat16(v.y - __bfloat162float(h1));
    ((__nv_bfloat162*)lo)[i * 2] = p;
    p.x = __float2bfloat16(v.z - __bfloat162float(h2));
    p.y = __float2bfloat16(v.w - __bfloat162float(h3));
    ((__nv_bfloat162*)lo)[i * 2 + 1] = p;
}

// ---------------------------------------------------------------------------
// Emulated-fp32 GEMM via wmma bf16 (3 products: hh + hl + lh):
//   C[M,N] = A[M,K] @ B[N,K]^T   (B stored N x K row-major = col-major K x N)
// CTA tile 64x128, 8 warps (2 m x 4 n), warp tile 32x32 (2x2 wmma frags),
// BK=32, cp.async double-buffered SMEM (pitch 80 B).
// MODE 0 (zg):  A = g_z{hi,lo},  B = g_wg_{hi,lo},  writes Cout (raw, no bias).
// MODE 1 (rec): A = g_h{hi,lo},  B = g_whh_{hi,lo}, writes g_partials[z]
//               (split-K over grid.z, kb = z*ksize).
// ---------------------------------------------------------------------------
#define SA_HI 0
#define SA_LO 5120
#define SB_HI 10240
#define SB_LO 20480
#define STAGE 30720
#define SMEMB (2 * STAGE)

template<int K, int MODE>
__global__ __launch_bounds__(256) void mma_gemm(float* __restrict__ Cout, int ksize)
{
    extern __shared__ char smem[];
    const uint32_t sb = (uint32_t)__cvta_generic_to_shared(smem);
    const int tid = threadIdx.x;
    const int wid = tid >> 5;
    const int wm = wid & 1;           // warp m index (0..1)
    const int wn = wid >> 1;          // warp n index (0..3)
    const int n0 = blockIdx.x * BN;
    const int m0 = blockIdx.y * BM;
    const int kb = (MODE == 1) ? (blockIdx.z * ksize) : 0;
    const int NIT = ksize / BK;

    // device-side selection of operand arrays (host must never pass these)
    const __nv_bfloat16* __restrict__ Ahi = (MODE == 0) ? g_zhi    : g_hhi;
    const __nv_bfloat16* __restrict__ Alo = (MODE == 0) ? g_zlo    : g_hlo;
    const __nv_bfloat16* __restrict__ Bhi = (MODE == 0) ? g_wg_hi  : g_whh_hi;
    const __nv_bfloat16* __restrict__ Blo = (MODE == 0) ? g_wg_lo  : g_whh_lo;

    const int lr = tid >> 2;          // 0..63
    const int lc = tid & 3;           // 16B chunk 0..3

    wmma::fragment<wmma::accumulator, 16, 16, 16, float> acc[2][2];
    #pragma unroll
    for (int f = 0; f < 2; f++)
        #pragma unroll
        for (int n = 0; n < 2; n++)
            wmma::fill_fragment(acc[f][n], 0.0f);

    auto issue = [&](int it, int buf) {
        const int koff = kb + it * BK;
        const uint32_t st = sb + buf * STAGE;
        const uint32_t rowoff = (uint32_t)(lr * 80 + lc * 16);
        const size_t ga = (size_t)(m0 + lr) * K + koff + lc * 8;
        cp16(st + SA_HI + rowoff, Ahi + ga);
        cp16(st + SA_LO + rowoff, Alo + ga);
        const size_t gb0 = (size_t)(n0 + lr) * K + koff + lc * 8;
        const size_t gb1 = (size_t)(n0 + lr + 64) * K + koff + lc * 8;
        const uint32_t rowoff1 = (uint32_t)((lr + 64) * 80 + lc * 16);
        cp16(st + SB_HI + rowoff,  Bhi + gb0);
        cp16(st + SB_LO + rowoff,  Blo + gb0);
        cp16(st + SB_HI + rowoff1, Bhi + gb1);
        cp16(st + SB_LO + rowoff1, Blo + gb1);
        cp_commit();
    };

    issue(0, 0);

    for (int kt = 0; kt < NIT; kt++) {
        if (kt + 1 < NIT) {
            issue(kt + 1, (kt + 1) & 1);
            cp_wait<1>();
        } else {
            cp_wait<0>();
        }
        __syncthreads();

        const char* stc = smem + (size_t)(kt & 1) * STAGE;
        const __nv_bfloat16* sAh = (const __nv_bfloat16*)(stc + SA_HI);
        const __nv_bfloat16* sAl = (const __nv_bfloat16*)(stc + SA_LO);
        const __nv_bfloat16* sBh = (const __nv_bfloat16*)(stc + SB_HI);
        const __nv_bfloat16* sBl = (const __nv_bfloat16*)(stc + SB_LO);

        #pragma unroll
        for (int ks = 0; ks < 2; ks++) {
            wmma::fragment<wmma::matrix_a, 16, 16, 16, __nv_bfloat16, wmma::row_major> ah[2], al[2];
            wmma::fragment<wmma::matrix_b, 16, 16, 16, __nv_bfloat16, wmma::col_major> bh[2], bl[2];
            #pragma unroll
            for (int f = 0; f < 2; f++) {
                const int r = wm * 32 + f * 16;
                wmma::load_matrix_sync(ah[f], sAh + r * APITCH + ks * 16, APITCH);
                wmma::load_matrix_sync(al[f], sAl + r * APITCH + ks * 16, APITCH);
            }
            #pragma unroll
            for (int n = 0; n < 2; n++) {
                const int r = wn * 32 + n * 16;
                wmma::load_matrix_sync(bh[n], sBh + r * APITCH + ks * 16, APITCH);
                wmma::load_matrix_sync(bl[n], sBl + r * APITCH + ks * 16, APITCH);
            }
            #pragma unroll
            for (int f = 0; f < 2; f++)
                #pragma unroll
                for (int n = 0; n < 2; n++) {
                    wmma::mma_sync(acc[f][n], ah[f], bh[n], acc[f][n]);
                    wmma::mma_sync(acc[f][n], ah[f], bl[n], acc[f][n]);
                    wmma::mma_sync(acc[f][n], al[f], bh[n], acc[f][n]);
                }
        }
        __syncthreads();
    }

    float* C = (MODE == 1) ? (g_partials + (size_t)blockIdx.z * (BB * DH)) : Cout;
    #pragma unroll
    for (int f = 0; f < 2; f++) {
        const int row = m0 + wm * 32 + f * 16;
        #pragma unroll
        for (int n = 0; n < 2; n++) {
            const int col = n0 + wn * 32 + n * 16;
            wmma::store_matrix_sync(C + (size_t)row * DH + col, acc[f][n],
                                    DH, wmma::mem_row_major);
        }
    }
}

// ---------------------------------------------------------------------------
// LayerNorm + ReLU. pre = dst(=zg_t raw) + bias + sum_{s<NS} partials[s].
// Writes h fp32 to dst and bf16 hi/lo splits for the next step's GEMM.
// ---------------------------------------------------------------------------
template<int NS>
__global__ __launch_bounds__(256) void ln_kernel(
    float* __restrict__ dst, const float* __restrict__ bias,
    const float* __restrict__ gamma, const float* __restrict__ beta)
{
    const int row = blockIdx.x;
    const int tid = threadIdx.x;
    const size_t base = (size_t)row * DH + tid * 4;
    float4 v = *(const float4*)(dst + base);
    {
        float4 bb = *(const float4*)(bias + tid * 4);
        v.x += bb.x; v.y += bb.y; v.z += bb.z; v.w += bb.w;
    }
    #pragma unroll
    for (int s = 0; s < NS; s++) {
        float4 p = *(const float4*)(g_partials + (size_t)s * (BB * DH) + base);
        v.x += p.x; v.y += p.y; v.z += p.z; v.w += p.w;
    }
    float s1 = v.x + v.y + v.z + v.w;
    float s2 = v.x * v.x + v.y * v.y + v.z * v.z + v.w * v.w;
    #pragma unroll
    for (int o = 16; o > 0; o >>= 1) {
        s1 += __shfl_xor_sync(0xffffffffu, s1, o);
        s2 += __shfl_xor_sync(0xffffffffu, s2, o);
    }
    __shared__ float r1[8], r2[8];
    const int wid = tid >> 5, lane = tid & 31;
    if (lane == 0) { r1[wid] = s1; r2[wid] = s2; }
    __syncthreads();
    if (wid == 0) {
        float a = (lane < 8) ? r1[lane] : 0.f;
        float b = (lane < 8) ? r2[lane] : 0.f;
        #pragma unroll
        for (int o = 4; o > 0; o >>= 1) {
            a += __shfl_xor_sync(0xffffffffu, a, o);
            b += __shfl_xor_sync(0xffffffffu, b, o);
        }
        if (lane == 0) { r1[0] = a; r2[0] = b; }
    }
    __syncthreads();
    const float mean = r1[0] * (1.0f / DH);
    const float var  = r2[0] * (1.0f / DH) - mean * mean;
    const float inv  = rsqrtf(var + LN_EPS);

    const float4 g = *(const float4*)(gamma + tid * 4);
    const float4 b = *(const float4*)(beta + tid * 4);
    float4 y;
    y.x = fmaxf((v.x - mean) * inv * g.x + b.x, 0.f);
    y.y = fmaxf((v.y - mean) * inv * g.y + b.y, 0.f);
    y.z = fmaxf((v.z - mean) * inv * g.z + b.z, 0.f);
    y.w = fmaxf((v.w - mean) * inv * g.w + b.w, 0.f);
    *(float4*)(dst + base) = y;

    __nv_bfloat16 h0 = __float2bfloat16(y.x);
    __nv_bfloat16 h1 = __float2bfloat16(y.y);
    __nv_bfloat16 h2 = __float2bfloat16(y.z);
    __nv_bfloat16 h3 = __float2bfloat16(y.w);
    __nv_bfloat162 p;
    p.x = h0; p.y = h1; *(__nv_bfloat162*)(g_hhi + base)     = p;
    p.x = h2; p.y = h3; *(__nv_bfloat162*)(g_hhi + base + 2) = p;
    p.x = __float2bfloat16(y.x - __bfloat162float(h0));
    p.y = __float2bfloat16(y.y - __bfloat162float(h1));
    *(__nv_bfloat162*)(g_hlo + base) = p;
    p.x = __float2bfloat16(y.z - __bfloat162float(h2));
    p.y = __float2bfloat16(y.w - __bfloat162float(h3));
    *(__nv_bfloat162*)(g_hlo + base + 2) = p;
}

// ---------------------------------------------------------------------------
// kernel_launch
// ---------------------------------------------------------------------------
extern "C" void kernel_launch(void* const* d_in, const int* in_sizes, int n_in,
                              void* d_out, int out_size)
{
    const float* z     = (const float*)d_in[0];   // [T,B,DG]
    const float* W_h   = (const float*)d_in[1];   // [DH,DH]
    const float* W_g   = (const float*)d_in[2];   // [DH,DG]
    const float* b_h   = (const float*)d_in[3];   // [DH]
    const float* gamma = (const float*)d_in[4];   // [DH]
    const float* beta  = (const float*)d_in[5];   // [DH]
    float* out = (float*)d_out;                   // [T,B,DH]

    cudaFuncSetAttribute(mma_gemm<DG, 0>,
                         cudaFuncAttributeMaxDynamicSharedMemorySize, SMEMB);
    cudaFuncSetAttribute(mma_gemm<DH, 1>,
                         cudaFuncAttributeMaxDynamicSharedMemorySize, SMEMB);

    // hi/lo bf16 splits
    split_kernel<0><<<(TT * BB * DG / 4 + 255) / 256, 256>>>(z, TT * BB * DG / 4);
    split_kernel<1><<<(DH * DH / 4 + 255) / 256, 256>>>(W_h, DH * DH / 4);
    split_kernel<2><<<(DH * DG / 4 + 255) / 256, 256>>>(W_g, DH * DG / 4);

    // zg(raw) = z @ W_g^T  ->  d_out   (M=32768, N=1024, K=512); bias added in LN
    mma_gemm<DG, 0><<<dim3(DH / BN, (TT * BB) / BM), 256, SMEMB>>>(out, DG);

    // t = 0: pre = zg_0 + bias (h0 = 0)
    ln_kernel<0><<<BB, 256>>>(out, b_h, gamma, beta);

    // recurrence
    for (int t = 1; t < TT; t++) {
        float* zg_t = out + (size_t)t * BB * DH;
        mma_gemm<DH, 1><<<dim3(DH / BN, BB / BM, NSPLIT), 256, SMEMB>>>(nullptr, KS);
        ln_kernel<NSPLIT><<<BB, 256>>>(zg_t, b_h, gamma, beta);
    }
}